// round 13
// baseline (speedup 1.0000x reference)
#include <cuda_runtime.h>
#include <cuda_fp16.h>
#include <cstdint>

// Problem constants
#define N_INN   50000
#define NC      64
#define NT      8
#define NE      800000
#define N_OUTN  50000
#define NF      64
#define KD      512   // NT*NC
#define NBLK_SCAN 196 // ceil(50000/256)

// GEMM tiling (fp16 A/B, fp32 accum)
#define BM      128
#define BK      64                         // k-elements per iter
#define NITER   (KD / BK)                  // 8
#define AS_STRIDE 36                       // words (uint32 = f16x2 pairs); 32 used + 4 pad
#define BS_STRIDE 72                       // words; 64 used + 8 pad (72 mod 32 = 8 -> bijection)
#define AS_WORDS  (BM * AS_STRIDE)         // 4608 / stage
#define BS_WORDS  ((BK / 2) * BS_STRIDE)   // 32*72 = 2304 / stage
#define GEMM_SMEM_WORDS (2 * AS_WORDS + 2 * BS_WORDS)
#define GEMM_SMEM_BYTES (GEMM_SMEM_WORDS * 4)   // 55296

// ---------------- scratch (static device allocations; zero-initialized at load) ----------------
static __device__ int      g_count[N_OUTN];     // re-zeroed by k_scan each run
static __device__ int      g_offset[N_OUTN + 1];
static __device__ int      g_cursor[N_OUTN];
static __device__ int      g_in_sorted[NE];
static __device__ float4   g_ef_sorted[NE * 2];            // 8 floats / edge, sorted
static __device__ __half   g_aggh[(size_t)N_OUTN * KD];    // fp16, 51.2 MB
static __device__ uint32_t g_khp[(KD / 2) * NF];           // Kmat as f16x2 pairs (k-major pairs)

// decoupled-lookback scan state (reset by k_hist every run)
static __device__ int g_vbid;
static __device__ int g_tstate[NBLK_SCAN];   // 0=invalid 1=aggregate 2=prefix
static __device__ int g_tagg[NBLK_SCAN];
static __device__ int g_tpref[NBLK_SCAN];

__device__ __forceinline__ int clampi(int v, int hi) {
    v = v < 0 ? 0 : v;
    return v >= hi ? hi - 1 : v;
}

__device__ __forceinline__ void cp16(uint32_t dst_smem, const void* src, bool valid) {
    int sz = valid ? 16 : 0;
    asm volatile("cp.async.cg.shared.global [%0], [%1], 16, %2;\n"
                 :: "r"(dst_smem), "l"(src), "r"(sz));
}

// ---------------- k1: histogram + Kmat fp16-pair conversion + scan-state reset ----------------
__global__ void k_hist(const int* __restrict__ idx, const float* __restrict__ Kmat) {
    int e = blockIdx.x * blockDim.x + threadIdx.x;
    if (e < (KD / 2) * NF) {
        int k2 = e >> 6;          // pair index
        int n  = e & 63;
        unsigned short lo = __half_as_ushort(__float2half(Kmat[(2 * k2) * 64 + n]));
        unsigned short hi = __half_as_ushort(__float2half(Kmat[(2 * k2 + 1) * 64 + n]));
        g_khp[e] = ((uint32_t)hi << 16) | lo;
    }
    if (e < NBLK_SCAN) g_tstate[e] = 0;
    if (e == 0) { g_vbid = 0; g_offset[N_OUTN] = NE; }
    if (e < NE) {
        int o = clampi(idx[2 * e], N_OUTN);
        atomicAdd(&g_count[o], 1);
    }
}

// ---------------- k2: single-kernel decoupled-lookback exclusive scan ----------------
__device__ __forceinline__ int block_scan_excl(int v, int* wsum, int* block_total) {
    int tid = threadIdx.x, lane = tid & 31, wid = tid >> 5;
    int x = v;
#pragma unroll
    for (int off = 1; off < 32; off <<= 1) {
        int y = __shfl_up_sync(0xffffffffu, x, off);
        if (lane >= off) x += y;
    }
    if (lane == 31) wsum[wid] = x;
    __syncthreads();
    if (tid == 0) {
        int run = 0;
#pragma unroll
        for (int j = 0; j < 8; j++) { int t = wsum[j]; wsum[j] = run; run += t; }
        *block_total = run;
    }
    __syncthreads();
    return x - v + wsum[wid];
}

__global__ __launch_bounds__(256) void k_scan() {
    __shared__ int wsum[8];
    __shared__ int btot;
    __shared__ int s_vbid;
    __shared__ int s_base;
    int tid = threadIdx.x;

    if (tid == 0) s_vbid = atomicAdd(&g_vbid, 1);
    __syncthreads();
    int vb = s_vbid;

    int i = vb * 256 + tid;
    int v = 0;
    if (i < N_OUTN) {
        v = g_count[i];
        g_count[i] = 0;                     // restore invariant for next run
    }
    int excl = block_scan_excl(v, wsum, &btot);

    if (tid == 0) {
        if (vb == 0) {
            g_tpref[0] = btot;
            __threadfence();
            *(volatile int*)&g_tstate[0] = 2;
            s_base = 0;
        } else {
            g_tagg[vb] = btot;
            __threadfence();
            *(volatile int*)&g_tstate[vb] = 1;
            // lookback
            int run = 0, j = vb - 1;
            while (true) {
                int st;
                do { st = *(volatile int*)&g_tstate[j]; } while (st == 0);
                __threadfence();            // acquire ordering for value read
                if (st == 2) { run += *(volatile int*)&g_tpref[j]; break; }
                run += *(volatile int*)&g_tagg[j];
                j--;                        // state[0] is always 2 -> terminates
            }
            s_base = run;
            g_tpref[vb] = run + btot;
            __threadfence();
            *(volatile int*)&g_tstate[vb] = 2;
        }
    }
    __syncthreads();

    int off = s_base + excl;
    if (i < N_OUTN) {
        g_offset[i] = off;
        g_cursor[i] = off;
    }
}

// ---------------- k3: permute edges into segment-sorted order ----------------
__global__ void k_permute(const int* __restrict__ idx,
                          const float* __restrict__ ef) {
    int e = blockIdx.x * blockDim.x + threadIdx.x;
    if (e >= NE) return;
    int o  = clampi(idx[2 * e],     N_OUTN);
    int in = clampi(idx[2 * e + 1], N_INN);
    int pos = atomicAdd(&g_cursor[o], 1);
    pos = clampi(pos, NE);
    g_in_sorted[pos] = in;
    float4 v0, v1;
    v0.x = ef[0 * NE + e]; v0.y = ef[1 * NE + e];
    v0.z = ef[2 * NE + e]; v0.w = ef[3 * NE + e];
    v1.x = ef[4 * NE + e]; v1.y = ef[5 * NE + e];
    v1.z = ef[6 * NE + e]; v1.w = ef[7 * NE + e];
    g_ef_sorted[pos * 2]     = v0;
    g_ef_sorted[pos * 2 + 1] = v1;
}

// ---------------- k4: aggregation — TWO warps per node (c-halves), fp16 output ----------------
__device__ __forceinline__ void fma8(float acc[8], float4 e0, float4 e1, float a) {
    acc[0] += e0.x * a;  acc[1] += e0.y * a;
    acc[2] += e0.z * a;  acc[3] += e0.w * a;
    acc[4] += e1.x * a;  acc[5] += e1.y * a;
    acc[6] += e1.z * a;  acc[7] += e1.w * a;
}

__global__ __launch_bounds__(256) void k_agg(const float* __restrict__ nf) {
    int gw2  = (blockIdx.x * blockDim.x + threadIdx.x) >> 5;  // global warp id
    int lane = threadIdx.x & 31;
    int node = gw2 >> 1;
    int half = gw2 & 1;
    if (node >= N_OUTN) return;
    int start = g_offset[node];
    int end   = g_offset[node + 1];
    int coff  = half * 32 + lane;

    float acc[8];
#pragma unroll
    for (int i = 0; i < 8; i++) acc[i] = 0.f;

    int p = start;
    for (; p + 2 <= end; p += 2) {
        int in0 = g_in_sorted[p];
        int in1 = g_in_sorted[p + 1];
        float4 e00 = g_ef_sorted[p * 2 + 0], e01 = g_ef_sorted[p * 2 + 1];
        float4 e10 = g_ef_sorted[p * 2 + 2], e11 = g_ef_sorted[p * 2 + 3];
        float a0 = nf[in0 * NC + coff];
        float a1 = nf[in1 * NC + coff];
        fma8(acc, e00, e01, a0);
        fma8(acc, e10, e11, a1);
    }
    if (p < end) {
        int in0 = g_in_sorted[p];
        float4 e00 = g_ef_sorted[p * 2], e01 = g_ef_sorted[p * 2 + 1];
        float a0 = nf[in0 * NC + coff];
        fma8(acc, e00, e01, a0);
    }

    __half* dst = g_aggh + (size_t)node * KD;
#pragma unroll
    for (int t = 0; t < NT; t++)
        dst[t * 64 + coff] = __float2half(acc[t]);
}

// ---------------- k5: fp16 GEMM (m16n8k16, fp32 accum), cp.async double-buffered ----------------
// out(50000x64) = Aggh(50000x512) @ Kh(512x64) + bias
// 256 threads (8 warps), BM=128, BK=64. Warp w: rows m0+16w..16w+15, full n=64.
extern __shared__ uint32_t sgm[];

__global__ __launch_bounds__(256) void k_gemm(const float* __restrict__ bias,
                                              float* __restrict__ out) {
    int tid  = threadIdx.x;
    int warp = tid >> 5;
    int lane = tid & 31;
    int gid  = lane >> 2;     // 0..7
    int tig  = lane & 3;      // 0..3
    int m0   = blockIdx.x * BM;

    uint32_t sbase = (uint32_t)__cvta_generic_to_shared(sgm);

    float acc[8][4];
#pragma unroll
    for (int nt = 0; nt < 8; nt++)
#pragma unroll
        for (int j = 0; j < 4; j++) acc[nt][j] = 0.f;

    // A stage: 128 rows x 64 halfs (128B) = 1024 x 16B chunks, 4/thread
    // B stage: 32 pair-rows x 64 uint32 = 512 x 16B chunks, 2/thread
    {
        const int k0 = 0, s = 0;
#pragma unroll
        for (int i = 0; i < 4; i++) {
            int q = tid + i * 256, row = q >> 3, c8 = q & 7;
            int gm = m0 + row;
            bool v = gm < N_OUTN;
            const __half* src = g_aggh + (size_t)(v ? gm : 0) * KD + k0 + c8 * 8;
            cp16(sbase + (s * AS_WORDS + row * AS_STRIDE + c8 * 4) * 4, src, v);
        }
#pragma unroll
        for (int i = 0; i < 2; i++) {
            int q = tid + i * 256, k2 = q >> 4, n4 = q & 15;
            cp16(sbase + (2 * AS_WORDS + s * BS_WORDS + k2 * BS_STRIDE + n4 * 4) * 4,
                 g_khp + k2 * 64 + n4 * 4, true);
        }
        asm volatile("cp.async.commit_group;\n");
    }

    for (int it = 0; it < NITER; it++) {
        if (it + 1 < NITER) {
            const int k0 = (it + 1) * BK, s = (it + 1) & 1;
#pragma unroll
            for (int i = 0; i < 4; i++) {
                int q = tid + i * 256, row = q >> 3, c8 = q & 7;
                int gm = m0 + row;
                bool v = gm < N_OUTN;
                const __half* src = g_aggh + (size_t)(v ? gm : 0) * KD + k0 + c8 * 8;
                cp16(sbase + (s * AS_WORDS + row * AS_STRIDE + c8 * 4) * 4, src, v);
            }
#pragma unroll
            for (int i = 0; i < 2; i++) {
                int q = tid + i * 256, k2 = q >> 4, n4 = q & 15;
                cp16(sbase + (2 * AS_WORDS + s * BS_WORDS + k2 * BS_STRIDE + n4 * 4) * 4,
                     g_khp + ((it + 1) * (BK / 2) + k2) * 64 + n4 * 4, true);
            }
            asm volatile("cp.async.commit_group;\n");
            asm volatile("cp.async.wait_group 1;\n");
        } else {
            asm volatile("cp.async.wait_group 0;\n");
        }
        __syncthreads();

        const uint32_t* As = sgm + (it & 1) * AS_WORDS;
        const uint32_t* Bs = sgm + 2 * AS_WORDS + (it & 1) * BS_WORDS;
        int wm = warp * 16;
        // kb = pair-index base; each step covers 16 k-elements (8 pairs)
#pragma unroll
        for (int kb = 0; kb < BK / 2; kb += 8) {
            uint32_t a0 = As[(wm + gid) * AS_STRIDE + kb + tig];
            uint32_t a1 = As[(wm + gid + 8) * AS_STRIDE + kb + tig];
            uint32_t a2 = As[(wm + gid) * AS_STRIDE + kb + tig + 4];
            uint32_t a3 = As[(wm + gid + 8) * AS_STRIDE + kb + tig + 4];
#pragma unroll
            for (int nt = 0; nt < 8; nt++) {
                int n = nt * 8 + gid;
                uint32_t b0 = Bs[(kb + tig) * BS_STRIDE + n];
                uint32_t b1 = Bs[(kb + tig + 4) * BS_STRIDE + n];
                asm volatile(
                    "mma.sync.aligned.m16n8k16.row.col.f32.f16.f16.f32 "
                    "{%0,%1,%2,%3}, {%4,%5,%6,%7}, {%8,%9}, {%0,%1,%2,%3};\n"
                    : "+f"(acc[nt][0]), "+f"(acc[nt][1]),
                      "+f"(acc[nt][2]), "+f"(acc[nt][3])
                    : "r"(a0), "r"(a1), "r"(a2), "r"(a3), "r"(b0), "r"(b1));
            }
        }
        __syncthreads();
    }

    int mA = m0 + warp * 16 + gid;
    int mB = mA + 8;
#pragma unroll
    for (int nt = 0; nt < 8; nt++) {
        int n = nt * 8 + tig * 2;
        float b0 = bias[n], b1 = bias[n + 1];
        if (mA < N_OUTN) {
            float2 v; v.x = acc[nt][0] + b0; v.y = acc[nt][1] + b1;
            *(float2*)(out + (size_t)mA * NF + n) = v;
        }
        if (mB < N_OUTN) {
            float2 v; v.x = acc[nt][2] + b0; v.y = acc[nt][3] + b1;
            *(float2*)(out + (size_t)mB * NF + n) = v;
        }
    }
}

// ---------------- launch ----------------
extern "C" void kernel_launch(void* const* d_in, const int* in_sizes, int n_in,
                              void* d_out, int out_size) {
    const float* nf   = (const float*)d_in[0];   // node_features (50000,64)
    const float* ef   = (const float*)d_in[1];   // edge_features (8,800000)
    const int*   idx  = (const int*)d_in[2];     // indices (800000,2) int32
    const float* Kmat = (const float*)d_in[3];   // kernel (8,64,64)
    const float* bias = (const float*)d_in[4];   // bias (64,)
    float*       out  = (float*)d_out;           // (50000,64)

    cudaFuncSetAttribute(k_gemm, cudaFuncAttributeMaxDynamicSharedMemorySize,
                         GEMM_SMEM_BYTES);

    k_hist   <<<(NE + 255) / 256, 256>>>(idx, Kmat);        // launch 0
    k_scan   <<<NBLK_SCAN, 256>>>();                        // launch 1
    k_permute<<<(NE + 255) / 256, 256>>>(idx, ef);          // launch 2
    k_agg    <<<(N_OUTN * 2 * 32 + 255) / 256, 256>>>(nf);  // launch 3 -> profiled
    k_gemm   <<<(N_OUTN + BM - 1) / BM, 256, GEMM_SMEM_BYTES>>>(bias, out);
}